// round 5
// baseline (speedup 1.0000x reference)
#include <cuda_runtime.h>
#include <cuda_bf16.h>
#include <cstdint>
#include <cstddef>

// ---------------------------------------------------------------------------
// out[B,O] = (x + sparse_pert) @ W + b
//          = x @ W + b + coeff * u[r] * W[idx[r], :]   (u = bitflip(g) - g)
// B=4096, F=16384, O=256, fp32.
//
// No tcgen05 on this toolchain (virtual arch compute_103 lacks the 'a'
// feature set) -> classic mma.sync.aligned.m16n8k16 bf16 GEMM, bf16x3 split
// (hi*hi + hi*lo + lo*hi), cp.async 4-stage pipeline, split-K=2 with
// atomicAdd into d_out pre-initialized with bias + rank-1 correction.
// ---------------------------------------------------------------------------

namespace {
constexpr int Bm = 4096;
constexpr int Fk = 16384;
constexpr int On = 256;

constexpr int BM = 128;
constexpr int BN = 128;
constexpr int BK = 32;
constexpr int SPLITK = 2;
constexpr int K_PER_CTA = Fk / SPLITK;     // 8192
constexpr int NT = K_PER_CTA / BK;         // 256 stages
constexpr int STAGES = 4;

// SMEM layout (bytes)
constexpr int RAWA_STAGE = BM * BK * 4;            // 16384 (fp32 x tile)
constexpr int BROW_PITCH = 80;                     // 64B data + 16B pad (bank-safe)
constexpr int B_STAGE = BN * BROW_PITCH;           // 10240 per (hi|lo)
constexpr int ACONV = BM * BROW_PITCH;             // 10240 per (hi|lo)

constexpr int OFF_RAWA = 0;                        // STAGES * 16384 = 65536
constexpr int OFF_BH   = OFF_RAWA + STAGES * RAWA_STAGE;          // 65536
constexpr int OFF_BL   = OFF_BH + STAGES * B_STAGE;               // 106496
constexpr int OFF_ACH  = OFF_BL + STAGES * B_STAGE;               // 147456
constexpr int OFF_ACL  = OFF_ACH + ACONV;                         // 157696
constexpr int SMEM_TOTAL = OFF_ACL + ACONV;                       // 167936
}  // namespace

// Pre-split/transposed W: Wt[n, k] bf16 hi/lo (8 MB each). Static scratch.
__device__ __align__(16) __nv_bfloat16 g_Wt_hi[(size_t)On * Fk];
__device__ __align__(16) __nv_bfloat16 g_Wt_lo[(size_t)On * Fk];

// ---------------------------- helpers --------------------------------------
__device__ __forceinline__ uint32_t smem_u32(const void* p) {
    uint32_t a;
    asm("{ .reg .u64 t; cvta.to.shared.u64 t, %1; cvt.u32.u64 %0, t; }"
        : "=r"(a) : "l"(p));
    return a;
}

__device__ __forceinline__ void cp_async16(void* dst, const void* src) {
    asm volatile("cp.async.cg.shared.global [%0], [%1], 16;"
                 :: "r"(smem_u32(dst)), "l"(src) : "memory");
}
__device__ __forceinline__ void cp_commit() {
    asm volatile("cp.async.commit_group;" ::: "memory");
}
template <int N>
__device__ __forceinline__ void cp_wait() {
    asm volatile("cp.async.wait_group %0;" :: "n"(N) : "memory");
}

// pack bf16(x1):bf16(x0) with x0 in the low half
__device__ __forceinline__ uint32_t cvt_bf16x2(float x1, float x0) {
    uint32_t d;
    asm("cvt.rn.bf16x2.f32 %0, %1, %2;" : "=r"(d) : "f"(x1), "f"(x0));
    return d;
}

__device__ __forceinline__ void mma_bf16(float c[4], const uint32_t a[4],
                                         const uint32_t b[2]) {
    asm volatile(
        "mma.sync.aligned.m16n8k16.row.col.f32.bf16.bf16.f32 "
        "{%0,%1,%2,%3},{%4,%5,%6,%7},{%8,%9},{%0,%1,%2,%3};"
        : "+f"(c[0]), "+f"(c[1]), "+f"(c[2]), "+f"(c[3])
        : "r"(a[0]), "r"(a[1]), "r"(a[2]), "r"(a[3]), "r"(b[0]), "r"(b[1]));
}

// ------------------- kernel 1: W transpose + bf16 split --------------------
__global__ void prep_w_kernel(const float* __restrict__ W) {
    __shared__ float t[32][33];
    int n0 = blockIdx.x * 32;
    int k0 = blockIdx.y * 32;
    int tx = threadIdx.x, ty = threadIdx.y;
#pragma unroll
    for (int j = 0; j < 4; j++) {
        int k = k0 + ty + j * 8;
        t[ty + j * 8][tx] = W[(size_t)k * On + n0 + tx];
    }
    __syncthreads();
#pragma unroll
    for (int j = 0; j < 4; j++) {
        int n = n0 + ty + j * 8;
        float v = t[tx][ty + j * 8];
        __nv_bfloat16 h = __float2bfloat16(v);
        float lo = v - __bfloat162float(h);
        size_t o = (size_t)n * Fk + k0 + tx;
        g_Wt_hi[o] = h;
        g_Wt_lo[o] = __float2bfloat16(lo);
    }
}

// ------------- kernel 2: out = b + coeff * u[r] * W[idx[r], :] -------------
__global__ void init_out_kernel(const float* __restrict__ x,
                                const float* __restrict__ W,
                                const float* __restrict__ b,
                                const float* __restrict__ coeff,
                                const int* __restrict__ idx,
                                const int* __restrict__ bitpos,
                                float* __restrict__ out) {
    int r = blockIdx.x;
    int c = threadIdx.x;
    int j = idx[r];
    float g = x[(size_t)r * Fk + j];
    int gi = __float_as_int(g) ^ (1 << bitpos[r]);
    float u = (__int_as_float(gi) - g) * coeff[0];
    out[(size_t)r * On + c] = b[c] + u * W[(size_t)j * On + c];
}

// ------------------- kernel 3: split-K bf16x3 mma.sync GEMM ----------------
__global__ void __launch_bounds__(256, 1)
gemm_kernel(const float* __restrict__ x, float* __restrict__ out) {
    extern __shared__ char smem[];
    char* rawA = smem + OFF_RAWA;
    char* BhS  = smem + OFF_BH;
    char* BlS  = smem + OFF_BL;
    char* AcH  = smem + OFF_ACH;
    char* AcL  = smem + OFF_ACL;

    const int tid = threadIdx.x;
    const int lane = tid & 31, w = tid >> 5;
    const int wm = w & 1, wn = w >> 1;       // warp grid 2(M) x 4(N)
    const int g = lane >> 2, q = lane & 3;

    const int m0 = blockIdx.x * BM;
    const int n0 = blockIdx.y * BN;
    const int kbase = blockIdx.z * K_PER_CTA;

    float acc[4][4][4];
#pragma unroll
    for (int i = 0; i < 4; i++)
#pragma unroll
        for (int j = 0; j < 4; j++)
#pragma unroll
            for (int r = 0; r < 4; r++) acc[i][j][r] = 0.0f;

    // ---- stage loader (always commits one group) ----
    auto issue = [&](int kt) {
        if (kt < NT) {
            int slot = kt & (STAGES - 1);
            const float* xg = x + (size_t)m0 * Fk + kbase + kt * BK;
            char* ra = rawA + slot * RAWA_STAGE;
#pragma unroll
            for (int i = 0; i < 4; i++) {
                int ch = tid + i * 256;           // 0..1023
                int row = ch >> 3, sub = ch & 7;
                cp_async16(ra + row * 128 + sub * 16,
                           xg + (size_t)row * Fk + sub * 4);
            }
            const __nv_bfloat16* wh =
                g_Wt_hi + (size_t)n0 * Fk + kbase + kt * BK;
            const __nv_bfloat16* wl =
                g_Wt_lo + (size_t)n0 * Fk + kbase + kt * BK;
            char* bh = BhS + slot * B_STAGE;
            char* bl = BlS + slot * B_STAGE;
#pragma unroll
            for (int i = 0; i < 2; i++) {
                int ch = tid + i * 256;           // 0..511
                int row = ch >> 2, sub = ch & 3;
                cp_async16(bh + row * BROW_PITCH + sub * 16,
                           wh + (size_t)row * Fk + sub * 8);
                cp_async16(bl + row * BROW_PITCH + sub * 16,
                           wl + (size_t)row * Fk + sub * 8);
            }
        }
        cp_commit();
    };

    issue(0); issue(1); issue(2);

    for (int kt = 0; kt < NT; kt++) {
        const int slot = kt & (STAGES - 1);
        cp_wait<2>();            // groups committed: 3+kt; ensures group kt done
        __syncthreads();         // data visible to all; prev mma done (Aconv safe)

        issue(kt + 3);

        // ---- convert raw x fp32 -> bf16 hi/lo in SMEM (each elem once) ----
        {
            const char* ra = rawA + slot * RAWA_STAGE;
            int row = tid >> 1, half = tid & 1;
            const float4* src = (const float4*)(ra + row * 128 + half * 64);
            uint32_t hpk[8], lpk[8];
#pragma unroll
            for (int v4 = 0; v4 < 4; v4++) {
                float4 v = src[v4];
                uint32_t h01 = cvt_bf16x2(v.y, v.x);
                uint32_t h23 = cvt_bf16x2(v.w, v.z);
                float f0 = __uint_as_float(h01 << 16);
                float f1 = __uint_as_float(h01 & 0xFFFF0000u);
                float f2 = __uint_as_float(h23 << 16);
                float f3 = __uint_as_float(h23 & 0xFFFF0000u);
                uint32_t l01 = cvt_bf16x2(v.y - f1, v.x - f0);
                uint32_t l23 = cvt_bf16x2(v.w - f3, v.z - f2);
                hpk[v4 * 2] = h01; hpk[v4 * 2 + 1] = h23;
                lpk[v4 * 2] = l01; lpk[v4 * 2 + 1] = l23;
            }
            uint4* dh = (uint4*)(AcH + row * BROW_PITCH + half * 32);
            uint4* dl = (uint4*)(AcL + row * BROW_PITCH + half * 32);
            dh[0] = make_uint4(hpk[0], hpk[1], hpk[2], hpk[3]);
            dh[1] = make_uint4(hpk[4], hpk[5], hpk[6], hpk[7]);
            dl[0] = make_uint4(lpk[0], lpk[1], lpk[2], lpk[3]);
            dl[1] = make_uint4(lpk[4], lpk[5], lpk[6], lpk[7]);
        }
        __syncthreads();

        // ---- MMA: 2 x k16, 3 products each ----
        const char* bh = BhS + slot * B_STAGE;
        const char* bl = BlS + slot * B_STAGE;
#pragma unroll
        for (int kk = 0; kk < 2; kk++) {
            uint32_t ah[4][4], al[4][4], bhf[4][2], blf[4][2];
#pragma unroll
            for (int mt = 0; mt < 4; mt++) {
                int row = wm * 64 + mt * 16 + g;
                uint32_t off = row * BROW_PITCH + q * 4 + kk * 32;
                ah[mt][0] = *(const uint32_t*)(AcH + off);
                ah[mt][1] = *(const uint32_t*)(AcH + off + 8 * BROW_PITCH);
                ah[mt][2] = *(const uint32_t*)(AcH + off + 16);
                ah[mt][3] = *(const uint32_t*)(AcH + off + 8 * BROW_PITCH + 16);
                al[mt][0] = *(const uint32_t*)(AcL + off);
                al[mt][1] = *(const uint32_t*)(AcL + off + 8 * BROW_PITCH);
                al[mt][2] = *(const uint32_t*)(AcL + off + 16);
                al[mt][3] = *(const uint32_t*)(AcL + off + 8 * BROW_PITCH + 16);
            }
#pragma unroll
            for (int nt = 0; nt < 4; nt++) {
                int row = wn * 32 + nt * 8 + g;
                uint32_t off = row * BROW_PITCH + q * 4 + kk * 32;
                bhf[nt][0] = *(const uint32_t*)(bh + off);
                bhf[nt][1] = *(const uint32_t*)(bh + off + 16);
                blf[nt][0] = *(const uint32_t*)(bl + off);
                blf[nt][1] = *(const uint32_t*)(bl + off + 16);
            }
#pragma unroll
            for (int mt = 0; mt < 4; mt++)
#pragma unroll
                for (int nt = 0; nt < 4; nt++) {
                    mma_bf16(acc[mt][nt], ah[mt], bhf[nt]);
                    mma_bf16(acc[mt][nt], ah[mt], blf[nt]);
                    mma_bf16(acc[mt][nt], al[mt], bhf[nt]);
                }
        }
    }

    cp_wait<0>();  // drain outstanding cp.async before exit

    // ---- epilogue: atomicAdd into pre-initialized out ----
#pragma unroll
    for (int mt = 0; mt < 4; mt++) {
        int r0 = m0 + wm * 64 + mt * 16 + g;
#pragma unroll
        for (int nt = 0; nt < 4; nt++) {
            int col = n0 + wn * 32 + nt * 8 + q * 2;
            float* p0 = out + (size_t)r0 * On + col;
            float* p1 = out + (size_t)(r0 + 8) * On + col;
            atomicAdd(p0,     acc[mt][nt][0]);
            atomicAdd(p0 + 1, acc[mt][nt][1]);
            atomicAdd(p1,     acc[mt][nt][2]);
            atomicAdd(p1 + 1, acc[mt][nt][3]);
        }
    }
}

// ---------------------------------------------------------------------------
extern "C" void kernel_launch(void* const* d_in, const int* in_sizes, int n_in,
                              void* d_out, int out_size) {
    const float* x      = (const float*)d_in[0];
    const float* W      = (const float*)d_in[1];
    const float* b      = (const float*)d_in[2];
    const float* coeff  = (const float*)d_in[3];
    const int*   idx    = (const int*)d_in[4];
    const int*   bitpos = (const int*)d_in[5];
    float* out = (float*)d_out;

    // Unconditional (no static guards allowed): idempotent, capture-safe.
    cudaFuncSetAttribute(gemm_kernel,
                         cudaFuncAttributeMaxDynamicSharedMemorySize,
                         SMEM_TOTAL);

    // 1) W -> transposed bf16 hi/lo scratch
    prep_w_kernel<<<dim3(On / 32, Fk / 32), dim3(32, 8)>>>(W);
    // 2) out = b + coeff*u*W[idx,:]
    init_out_kernel<<<Bm, On>>>(x, W, b, coeff, idx, bitpos, out);
    // 3) out += x @ W  (split-K, atomics)
    gemm_kernel<<<dim3(Bm / BM, On / BN, SPLITK), 256, SMEM_TOTAL>>>(x, out);
}

// round 7
// speedup vs baseline: 1.7196x; 1.7196x over previous
#include <cuda_runtime.h>
#include <cuda_fp16.h>
#include <cstdint>
#include <cstddef>

// ---------------------------------------------------------------------------
// out[B,O] = (x + sparse_pert) @ W + b
//          = x @ W + b + coeff * u[r] * W[idx[r], :]   (u = bitflip(g) - g)
// B=4096, F=16384, O=256, fp32.
//
// Single-pass fp16 mma.sync GEMM (R5 measured bf16x3 at 428us -> HMMA
// rt=16cyc/SMSP; 1 pass ~ 138us compute). fp16 input-rounding gives norm
// rel_err ~4e-4 < 1e-3 gate; accumulation is fp32 on both paths.
// ---------------------------------------------------------------------------

namespace {
constexpr int Bm = 4096;
constexpr int Fk = 16384;
constexpr int On = 256;

constexpr int BM = 128;
constexpr int BN = 128;
constexpr int BK = 32;
constexpr int SPLITK = 2;
constexpr int K_PER_CTA = Fk / SPLITK;     // 8192
constexpr int NT = K_PER_CTA / BK;         // 256 stages
constexpr int STAGES = 4;

// SMEM layout (bytes)
constexpr int RAWA_STAGE = BM * BK * 4;            // 16384 (fp32 x tile)
constexpr int BROW_PITCH = 80;                     // 64B data + 16B pad
constexpr int B_STAGE = BN * BROW_PITCH;           // 10240
constexpr int ACONV = BM * BROW_PITCH;             // 10240

constexpr int OFF_RAWA = 0;                                        // 65536
constexpr int OFF_B    = OFF_RAWA + STAGES * RAWA_STAGE;           // 65536
constexpr int OFF_AC   = OFF_B + STAGES * B_STAGE;                 // 106496
constexpr int SMEM_TOTAL = OFF_AC + ACONV;                         // 116736
}  // namespace

// Pre-transposed W: Wt[n, k] fp16 (8 MB). Static scratch.
__device__ __align__(16) __half g_Wt[(size_t)On * Fk];

// ---------------------------- helpers --------------------------------------
__device__ __forceinline__ uint32_t smem_u32(const void* p) {
    uint32_t a;
    asm("{ .reg .u64 t; cvta.to.shared.u64 t, %1; cvt.u32.u64 %0, t; }"
        : "=r"(a) : "l"(p));
    return a;
}

__device__ __forceinline__ void cp_async16(void* dst, const void* src) {
    asm volatile("cp.async.cg.shared.global [%0], [%1], 16;"
                 :: "r"(smem_u32(dst)), "l"(src) : "memory");
}
__device__ __forceinline__ void cp_commit() {
    asm volatile("cp.async.commit_group;" ::: "memory");
}
template <int N>
__device__ __forceinline__ void cp_wait() {
    asm volatile("cp.async.wait_group %0;" :: "n"(N) : "memory");
}

// pack f16(x1):f16(x0), x0 in low half
__device__ __forceinline__ uint32_t cvt_f16x2(float x1, float x0) {
    uint32_t d;
    asm("cvt.rn.f16x2.f32 %0, %1, %2;" : "=r"(d) : "f"(x1), "f"(x0));
    return d;
}

__device__ __forceinline__ void mma_f16(float c[4], const uint32_t a[4],
                                        const uint32_t b[2]) {
    asm volatile(
        "mma.sync.aligned.m16n8k16.row.col.f32.f16.f16.f32 "
        "{%0,%1,%2,%3},{%4,%5,%6,%7},{%8,%9},{%0,%1,%2,%3};"
        : "+f"(c[0]), "+f"(c[1]), "+f"(c[2]), "+f"(c[3])
        : "r"(a[0]), "r"(a[1]), "r"(a[2]), "r"(a[3]), "r"(b[0]), "r"(b[1]));
}

// ------------------- kernel 1: W transpose to fp16 -------------------------
__global__ void prep_w_kernel(const float* __restrict__ W) {
    __shared__ float t[32][33];
    int n0 = blockIdx.x * 32;
    int k0 = blockIdx.y * 32;
    int tx = threadIdx.x, ty = threadIdx.y;
#pragma unroll
    for (int j = 0; j < 4; j++) {
        int k = k0 + ty + j * 8;
        t[ty + j * 8][tx] = W[(size_t)k * On + n0 + tx];
    }
    __syncthreads();
#pragma unroll
    for (int j = 0; j < 4; j++) {
        int n = n0 + ty + j * 8;
        float v = t[tx][ty + j * 8];
        g_Wt[(size_t)n * Fk + k0 + tx] = __float2half_rn(v);
    }
}

// ------------- kernel 2: out = b + coeff * u[r] * W[idx[r], :] -------------
__global__ void init_out_kernel(const float* __restrict__ x,
                                const float* __restrict__ W,
                                const float* __restrict__ b,
                                const float* __restrict__ coeff,
                                const int* __restrict__ idx,
                                const int* __restrict__ bitpos,
                                float* __restrict__ out) {
    int r = blockIdx.x;
    int c = threadIdx.x;
    int j = idx[r];
    float g = x[(size_t)r * Fk + j];
    int gi = __float_as_int(g) ^ (1 << bitpos[r]);
    float u = (__int_as_float(gi) - g) * coeff[0];
    out[(size_t)r * On + c] = b[c] + u * W[(size_t)j * On + c];
}

// ------------------- kernel 3: split-K fp16 mma.sync GEMM ------------------
__global__ void __launch_bounds__(256, 1)
gemm_kernel(const float* __restrict__ x, float* __restrict__ out) {
    extern __shared__ char smem[];
    char* rawA = smem + OFF_RAWA;
    char* BS   = smem + OFF_B;
    char* Ac   = smem + OFF_AC;

    const int tid = threadIdx.x;
    const int lane = tid & 31, w = tid >> 5;
    const int wm = w & 1, wn = w >> 1;       // warp grid 2(M) x 4(N)
    const int g = lane >> 2, q = lane & 3;

    const int m0 = blockIdx.x * BM;
    const int n0 = blockIdx.y * BN;
    const int kbase = blockIdx.z * K_PER_CTA;

    float acc[4][4][4];
#pragma unroll
    for (int i = 0; i < 4; i++)
#pragma unroll
        for (int j = 0; j < 4; j++)
#pragma unroll
            for (int r = 0; r < 4; r++) acc[i][j][r] = 0.0f;

    // ---- stage loader (always commits one group) ----
    auto issue = [&](int kt) {
        if (kt < NT) {
            int slot = kt & (STAGES - 1);
            const float* xg = x + (size_t)m0 * Fk + kbase + kt * BK;
            char* ra = rawA + slot * RAWA_STAGE;
#pragma unroll
            for (int i = 0; i < 4; i++) {
                int ch = tid + i * 256;           // 0..1023
                int row = ch >> 3, sub = ch & 7;
                cp_async16(ra + row * 128 + sub * 16,
                           xg + (size_t)row * Fk + sub * 4);
            }
            const __half* wt = g_Wt + (size_t)n0 * Fk + kbase + kt * BK;
            char* bs = BS + slot * B_STAGE;
#pragma unroll
            for (int i = 0; i < 2; i++) {
                int ch = tid + i * 256;           // 0..511
                int row = ch >> 2, sub = ch & 3;
                cp_async16(bs + row * BROW_PITCH + sub * 16,
                           wt + (size_t)row * Fk + sub * 8);
            }
        }
        cp_commit();
    };

    issue(0); issue(1); issue(2);

    for (int kt = 0; kt < NT; kt++) {
        const int slot = kt & (STAGES - 1);
        cp_wait<2>();            // groups committed: 3+kt; group kt complete
        __syncthreads();         // data visible; prev mma done (Ac reuse safe)

        issue(kt + 3);

        // ---- convert raw x fp32 -> fp16 in SMEM (each elem once) ----
        {
            const char* ra = rawA + slot * RAWA_STAGE;
            int row = tid >> 1, half = tid & 1;
            const float4* src = (const float4*)(ra + row * 128 + half * 64);
            uint32_t pk[8];
#pragma unroll
            for (int v4 = 0; v4 < 4; v4++) {
                float4 v = src[v4];
                pk[v4 * 2]     = cvt_f16x2(v.y, v.x);
                pk[v4 * 2 + 1] = cvt_f16x2(v.w, v.z);
            }
            uint4* d = (uint4*)(Ac + row * BROW_PITCH + half * 32);
            d[0] = make_uint4(pk[0], pk[1], pk[2], pk[3]);
            d[1] = make_uint4(pk[4], pk[5], pk[6], pk[7]);
        }
        __syncthreads();

        // ---- MMA: 2 x k16 ----
        const char* bs = BS + slot * B_STAGE;
#pragma unroll
        for (int kk = 0; kk < 2; kk++) {
            uint32_t af[4][4], bf[4][2];
#pragma unroll
            for (int mt = 0; mt < 4; mt++) {
                int row = wm * 64 + mt * 16 + g;
                uint32_t off = row * BROW_PITCH + q * 4 + kk * 32;
                af[mt][0] = *(const uint32_t*)(Ac + off);
                af[mt][1] = *(const uint32_t*)(Ac + off + 8 * BROW_PITCH);
                af[mt][2] = *(const uint32_t*)(Ac + off + 16);
                af[mt][3] = *(const uint32_t*)(Ac + off + 8 * BROW_PITCH + 16);
            }
#pragma unroll
            for (int nt = 0; nt < 4; nt++) {
                int row = wn * 32 + nt * 8 + g;
                uint32_t off = row * BROW_PITCH + q * 4 + kk * 32;
                bf[nt][0] = *(const uint32_t*)(bs + off);
                bf[nt][1] = *(const uint32_t*)(bs + off + 16);
            }
#pragma unroll
            for (int mt = 0; mt < 4; mt++)
#pragma unroll
                for (int nt = 0; nt < 4; nt++)
                    mma_f16(acc[mt][nt], af[mt], bf[nt]);
        }
    }

    cp_wait<0>();  // drain outstanding cp.async before exit

    // ---- epilogue: atomicAdd into pre-initialized out ----
#pragma unroll
    for (int mt = 0; mt < 4; mt++) {
        int r0 = m0 + wm * 64 + mt * 16 + g;
#pragma unroll
        for (int nt = 0; nt < 4; nt++) {
            int col = n0 + wn * 32 + nt * 8 + q * 2;
            float* p0 = out + (size_t)r0 * On + col;
            float* p1 = out + (size_t)(r0 + 8) * On + col;
            atomicAdd(p0,     acc[mt][nt][0]);
            atomicAdd(p0 + 1, acc[mt][nt][1]);
            atomicAdd(p1,     acc[mt][nt][2]);
            atomicAdd(p1 + 1, acc[mt][nt][3]);
        }
    }
}

// ---------------------------------------------------------------------------
extern "C" void kernel_launch(void* const* d_in, const int* in_sizes, int n_in,
                              void* d_out, int out_size) {
    const float* x      = (const float*)d_in[0];
    const float* W      = (const float*)d_in[1];
    const float* b      = (const float*)d_in[2];
    const float* coeff  = (const float*)d_in[3];
    const int*   idx    = (const int*)d_in[4];
    const int*   bitpos = (const int*)d_in[5];
    float* out = (float*)d_out;

    cudaFuncSetAttribute(gemm_kernel,
                         cudaFuncAttributeMaxDynamicSharedMemorySize,
                         SMEM_TOTAL);

    // 1) W -> transposed fp16 scratch
    prep_w_kernel<<<dim3(On / 32, Fk / 32), dim3(32, 8)>>>(W);
    // 2) out = b + coeff*u*W[idx,:]
    init_out_kernel<<<Bm, On>>>(x, W, b, coeff, idx, bitpos, out);
    // 3) out += x @ W  (split-K, atomics)
    gemm_kernel<<<dim3(Bm / BM, On / BN, SPLITK), 256, SMEM_TOTAL>>>(x, out);
}

// round 8
// speedup vs baseline: 2.5683x; 1.4936x over previous
#include <cuda_runtime.h>
#include <cuda_fp16.h>
#include <cstdint>
#include <cstddef>

// ---------------------------------------------------------------------------
// out[B,O] = (x + sparse_pert) @ W + b
//          = x @ W + b + coeff * u[r] * W[idx[r], :]   (u = bitflip(g) - g)
// B=4096, F=16384, O=256, fp32.
//
// R8: fp16 mma.sync GEMM. vs R7 (248.9us): BN=256 (x read once, overhead
// amortized over 2x MMA/stage), ldmatrix.x4 fragment loads, bank-conflict-
// free convert (XOR-swizzled rawA chunks + warp-remapped rows).
// ---------------------------------------------------------------------------

namespace {
constexpr int Bm = 4096;
constexpr int Fk = 16384;
constexpr int On = 256;

constexpr int BM = 128;
constexpr int BN = 256;                    // full O per CTA
constexpr int BK = 32;
constexpr int SPLITK = 4;
constexpr int K_PER_CTA = Fk / SPLITK;     // 4096
constexpr int NT = K_PER_CTA / BK;         // 128 stages
constexpr int STAGES = 4;

// SMEM layout (bytes)
constexpr int RAWA_STAGE = BM * BK * 4;            // 16384 (fp32 x tile)
constexpr int BROW_PITCH = 80;                     // 64B data + 16B pad
constexpr int B_STAGE = BN * BROW_PITCH;           // 20480
constexpr int ACONV = BM * BROW_PITCH;             // 10240

constexpr int OFF_RAWA = 0;                                        // 65536
constexpr int OFF_B    = OFF_RAWA + STAGES * RAWA_STAGE;           // 65536
constexpr int OFF_AC   = OFF_B + STAGES * B_STAGE;                 // 147456
constexpr int SMEM_TOTAL = OFF_AC + ACONV;                         // 157696
}  // namespace

// Pre-transposed W: Wt[n, k] fp16 (8 MB). Static scratch.
__device__ __align__(16) __half g_Wt[(size_t)On * Fk];

// ---------------------------- helpers --------------------------------------
__device__ __forceinline__ uint32_t smem_u32(const void* p) {
    uint32_t a;
    asm("{ .reg .u64 t; cvta.to.shared.u64 t, %1; cvt.u32.u64 %0, t; }"
        : "=r"(a) : "l"(p));
    return a;
}

__device__ __forceinline__ void cp_async16(void* dst, const void* src) {
    asm volatile("cp.async.cg.shared.global [%0], [%1], 16;"
                 :: "r"(smem_u32(dst)), "l"(src) : "memory");
}
__device__ __forceinline__ void cp_commit() {
    asm volatile("cp.async.commit_group;" ::: "memory");
}
template <int N>
__device__ __forceinline__ void cp_wait() {
    asm volatile("cp.async.wait_group %0;" :: "n"(N) : "memory");
}

// pack f16(x1):f16(x0), x0 in low half
__device__ __forceinline__ uint32_t cvt_f16x2(float x1, float x0) {
    uint32_t d;
    asm("cvt.rn.f16x2.f32 %0, %1, %2;" : "=r"(d) : "f"(x1), "f"(x0));
    return d;
}

__device__ __forceinline__ void ldsm_x4(uint32_t r[4], uint32_t addr) {
    asm volatile(
        "ldmatrix.sync.aligned.m8n8.x4.shared.b16 {%0,%1,%2,%3}, [%4];"
        : "=r"(r[0]), "=r"(r[1]), "=r"(r[2]), "=r"(r[3]) : "r"(addr));
}

__device__ __forceinline__ void mma_f16(float c[4], const uint32_t a[4],
                                        const uint32_t b[2]) {
    asm volatile(
        "mma.sync.aligned.m16n8k16.row.col.f32.f16.f16.f32 "
        "{%0,%1,%2,%3},{%4,%5,%6,%7},{%8,%9},{%0,%1,%2,%3};"
        : "+f"(c[0]), "+f"(c[1]), "+f"(c[2]), "+f"(c[3])
        : "r"(a[0]), "r"(a[1]), "r"(a[2]), "r"(a[3]), "r"(b[0]), "r"(b[1]));
}

// ------------------- kernel 1: W transpose to fp16 -------------------------
__global__ void prep_w_kernel(const float* __restrict__ W) {
    __shared__ float t[32][33];
    int n0 = blockIdx.x * 32;
    int k0 = blockIdx.y * 32;
    int tx = threadIdx.x, ty = threadIdx.y;
#pragma unroll
    for (int j = 0; j < 4; j++) {
        int k = k0 + ty + j * 8;
        t[ty + j * 8][tx] = W[(size_t)k * On + n0 + tx];
    }
    __syncthreads();
#pragma unroll
    for (int j = 0; j < 4; j++) {
        int n = n0 + ty + j * 8;
        float v = t[tx][ty + j * 8];
        g_Wt[(size_t)n * Fk + k0 + tx] = __float2half_rn(v);
    }
}

// ------------- kernel 2: out = b + coeff * u[r] * W[idx[r], :] -------------
__global__ void init_out_kernel(const float* __restrict__ x,
                                const float* __restrict__ W,
                                const float* __restrict__ b,
                                const float* __restrict__ coeff,
                                const int* __restrict__ idx,
                                const int* __restrict__ bitpos,
                                float* __restrict__ out) {
    int r = blockIdx.x;
    int c = threadIdx.x;
    int j = idx[r];
    float g = x[(size_t)r * Fk + j];
    int gi = __float_as_int(g) ^ (1 << bitpos[r]);
    float u = (__int_as_float(gi) - g) * coeff[0];
    out[(size_t)r * On + c] = b[c] + u * W[(size_t)j * On + c];
}

// ------------------- kernel 3: split-K fp16 mma.sync GEMM ------------------
__global__ void __launch_bounds__(256, 1)
gemm_kernel(const float* __restrict__ x, float* __restrict__ out) {
    extern __shared__ char smem[];
    char* rawA = smem + OFF_RAWA;
    char* BS   = smem + OFF_B;
    char* Ac   = smem + OFF_AC;

    const int tid = threadIdx.x;
    const int lane = tid & 31, w = tid >> 5;
    const int wm = w & 1, wn = w >> 1;       // warp grid 2(M) x 4(N), 64x64 tile
    const int g = lane >> 2, q = lane & 3;

    const int m0 = blockIdx.x * BM;
    const int kbase = blockIdx.z * K_PER_CTA;

    // ldmatrix per-lane address components (row within 16, k-16B half)
    const int lrow = lane & 15;
    const int lk16 = (lane >> 4) * 16;

    float acc[4][8][4];
#pragma unroll
    for (int i = 0; i < 4; i++)
#pragma unroll
        for (int j = 0; j < 8; j++)
#pragma unroll
            for (int r = 0; r < 4; r++) acc[i][j][r] = 0.0f;

    // ---- stage loader (always commits one group) ----
    auto issue = [&](int kt) {
        if (kt < NT) {
            int slot = kt & (STAGES - 1);
            const float* xg = x + (size_t)m0 * Fk + kbase + kt * BK;
            char* ra = rawA + slot * RAWA_STAGE;
#pragma unroll
            for (int i = 0; i < 4; i++) {
                int ch = tid + i * 256;           // 0..1023
                int row = ch >> 3, sub = ch & 7;
                int phys = sub ^ (row & 7);       // XOR swizzle (bank-free reads)
                cp_async16(ra + row * 128 + phys * 16,
                           xg + (size_t)row * Fk + sub * 4);
            }
            const __half* wt = g_Wt + kbase + kt * BK;
            char* bs = BS + slot * B_STAGE;
#pragma unroll
            for (int i = 0; i < 4; i++) {
                int ch = tid + i * 256;           // 0..1023
                int row = ch >> 2, sub = ch & 3;  // row 0..255
                cp_async16(bs + row * BROW_PITCH + sub * 16,
                           wt + (size_t)row * Fk + sub * 8);
            }
        }
        cp_commit();
    };

    issue(0); issue(1); issue(2);

    // convert-thread mapping: conflict-free LDS.128 + STS.128
    const int crow = (w & 3) * 32 + lane;   // 0..127
    const int chh  = w >> 2;                // half of the 32-float row

    for (int kt = 0; kt < NT; kt++) {
        const int slot = kt & (STAGES - 1);
        cp_wait<2>();            // groups committed: 3+kt; group kt complete
        __syncthreads();         // data visible; prev mma done (Ac reuse safe)

        issue(kt + 3);

        // ---- convert raw x fp32 -> fp16 in SMEM (each elem once) ----
        {
            const char* ra = rawA + slot * RAWA_STAGE;
            uint32_t pk[8];
#pragma unroll
            for (int i = 0; i < 4; i++) {
                int phys = (chh * 4 + i) ^ (crow & 7);
                float4 v = *(const float4*)(ra + crow * 128 + phys * 16);
                pk[i * 2]     = cvt_f16x2(v.y, v.x);
                pk[i * 2 + 1] = cvt_f16x2(v.w, v.z);
            }
            uint4* d = (uint4*)(Ac + crow * BROW_PITCH + chh * 32);
            d[0] = make_uint4(pk[0], pk[1], pk[2], pk[3]);
            d[1] = make_uint4(pk[4], pk[5], pk[6], pk[7]);
        }
        __syncthreads();

        // ---- MMA: 2 x k16, ldmatrix fragment loads ----
        const uint32_t aBase = smem_u32(Ac) +
            (wm * 64 + lrow) * BROW_PITCH + lk16;
        const uint32_t bBase = smem_u32(BS) + slot * B_STAGE +
            (wn * 64 + lrow) * BROW_PITCH + lk16;
#pragma unroll
        for (int kk = 0; kk < 2; kk++) {
            uint32_t af[4][4];
#pragma unroll
            for (int mt = 0; mt < 4; mt++)
                ldsm_x4(af[mt], aBase + mt * 16 * BROW_PITCH + kk * 32);
            uint32_t bf[8][2];
#pragma unroll
            for (int p = 0; p < 4; p++) {
                uint32_t r[4];
                ldsm_x4(r, bBase + p * 16 * BROW_PITCH + kk * 32);
                bf[2 * p][0] = r[0]; bf[2 * p + 1][0] = r[1];
                bf[2 * p][1] = r[2]; bf[2 * p + 1][1] = r[3];
            }
#pragma unroll
            for (int mt = 0; mt < 4; mt++)
#pragma unroll
                for (int nt = 0; nt < 8; nt++)
                    mma_f16(acc[mt][nt], af[mt], bf[nt]);
        }
    }

    cp_wait<0>();  // drain outstanding cp.async before exit

    // ---- epilogue: atomicAdd into pre-initialized out ----
#pragma unroll
    for (int mt = 0; mt < 4; mt++) {
        int r0 = m0 + wm * 64 + mt * 16 + g;
#pragma unroll
        for (int nt = 0; nt < 8; nt++) {
            int col = wn * 64 + nt * 8 + q * 2;
            float* p0 = out + (size_t)r0 * On + col;
            float* p1 = out + (size_t)(r0 + 8) * On + col;
            atomicAdd(p0,     acc[mt][nt][0]);
            atomicAdd(p0 + 1, acc[mt][nt][1]);
            atomicAdd(p1,     acc[mt][nt][2]);
            atomicAdd(p1 + 1, acc[mt][nt][3]);
        }
    }
}

// ---------------------------------------------------------------------------
extern "C" void kernel_launch(void* const* d_in, const int* in_sizes, int n_in,
                              void* d_out, int out_size) {
    const float* x      = (const float*)d_in[0];
    const float* W      = (const float*)d_in[1];
    const float* b      = (const float*)d_in[2];
    const float* coeff  = (const float*)d_in[3];
    const int*   idx    = (const int*)d_in[4];
    const int*   bitpos = (const int*)d_in[5];
    float* out = (float*)d_out;

    cudaFuncSetAttribute(gemm_kernel,
                         cudaFuncAttributeMaxDynamicSharedMemorySize,
                         SMEM_TOTAL);

    // 1) W -> transposed fp16 scratch
    prep_w_kernel<<<dim3(On / 32, Fk / 32), dim3(32, 8)>>>(W);
    // 2) out = b + coeff*u*W[idx,:]
    init_out_kernel<<<Bm, On>>>(x, W, b, coeff, idx, bitpos, out);
    // 3) out += x @ W  (split-K=4, atomics; BN=256 so x is read once)
    gemm_kernel<<<dim3(Bm / BM, 1, SPLITK), 256, SMEM_TOTAL>>>(x, out);
}

// round 9
// speedup vs baseline: 2.6455x; 1.0301x over previous
#include <cuda_runtime.h>
#include <cuda_fp16.h>
#include <cstdint>
#include <cstddef>

// ---------------------------------------------------------------------------
// out[B,O] = (x + sparse_pert) @ W + b
//          = x @ W + b + coeff * u[r] * W[idx[r], :]   (u = bitflip(g) - g)
// B=4096, F=16384, O=256, fp32.
//
// R9: fp16 mma.sync GEMM at ~92% of the HMMA-fallback issue floor
// (rt=16cyc/SMSP, measured R5/R7/R8). vs R8 (166.6us): rank-1 init fused
// into the gemm prologue (single-wave residency: 128 CTAs <= 148 SMs at
// occ 1 -> init done ~1us, epilogue atomics ~150us), 5-stage pipeline.
// ---------------------------------------------------------------------------

namespace {
constexpr int Bm = 4096;
constexpr int Fk = 16384;
constexpr int On = 256;

constexpr int BM = 128;
constexpr int BK = 32;
constexpr int SPLITK = 4;
constexpr int K_PER_CTA = Fk / SPLITK;     // 4096
constexpr int NT = K_PER_CTA / BK;         // 128 stages
constexpr int STAGES = 5;

// SMEM layout (bytes)
constexpr int RAWA_STAGE = BM * BK * 4;            // 16384 (fp32 x tile)
constexpr int BROW_PITCH = 80;                     // 64B data + 16B pad
constexpr int B_STAGE = 256 * BROW_PITCH;          // 20480
constexpr int ACONV = BM * BROW_PITCH;             // 10240

constexpr int OFF_RAWA = 0;                                        // 81920
constexpr int OFF_B    = OFF_RAWA + STAGES * RAWA_STAGE;           // 81920
constexpr int OFF_AC   = OFF_B + STAGES * B_STAGE;                 // 184320
constexpr int SMEM_TOTAL = OFF_AC + ACONV;                         // 194560
}  // namespace

// Pre-transposed W: Wt[n, k] fp16 (8 MB). Static scratch.
__device__ __align__(16) __half g_Wt[(size_t)On * Fk];

// ---------------------------- helpers --------------------------------------
__device__ __forceinline__ uint32_t smem_u32(const void* p) {
    uint32_t a;
    asm("{ .reg .u64 t; cvta.to.shared.u64 t, %1; cvt.u32.u64 %0, t; }"
        : "=r"(a) : "l"(p));
    return a;
}

__device__ __forceinline__ void cp_async16(void* dst, const void* src) {
    asm volatile("cp.async.cg.shared.global [%0], [%1], 16;"
                 :: "r"(smem_u32(dst)), "l"(src) : "memory");
}
__device__ __forceinline__ void cp_commit() {
    asm volatile("cp.async.commit_group;" ::: "memory");
}
template <int N>
__device__ __forceinline__ void cp_wait() {
    asm volatile("cp.async.wait_group %0;" :: "n"(N) : "memory");
}

// pack f16(x1):f16(x0), x0 in low half
__device__ __forceinline__ uint32_t cvt_f16x2(float x1, float x0) {
    uint32_t d;
    asm("cvt.rn.f16x2.f32 %0, %1, %2;" : "=r"(d) : "f"(x1), "f"(x0));
    return d;
}

__device__ __forceinline__ void ldsm_x4(uint32_t r[4], uint32_t addr) {
    asm volatile(
        "ldmatrix.sync.aligned.m8n8.x4.shared.b16 {%0,%1,%2,%3}, [%4];"
        : "=r"(r[0]), "=r"(r[1]), "=r"(r[2]), "=r"(r[3]) : "r"(addr));
}

__device__ __forceinline__ void mma_f16(float c[4], const uint32_t a[4],
                                        const uint32_t b[2]) {
    asm volatile(
        "mma.sync.aligned.m16n8k16.row.col.f32.f16.f16.f32 "
        "{%0,%1,%2,%3},{%4,%5,%6,%7},{%8,%9},{%0,%1,%2,%3};"
        : "+f"(c[0]), "+f"(c[1]), "+f"(c[2]), "+f"(c[3])
        : "r"(a[0]), "r"(a[1]), "r"(a[2]), "r"(a[3]), "r"(b[0]), "r"(b[1]));
}

// ------------------- kernel 1: W transpose to fp16 -------------------------
__global__ void prep_w_kernel(const float* __restrict__ W) {
    __shared__ float t[32][33];
    int n0 = blockIdx.x * 32;
    int k0 = blockIdx.y * 32;
    int tx = threadIdx.x, ty = threadIdx.y;
#pragma unroll
    for (int j = 0; j < 4; j++) {
        int k = k0 + ty + j * 8;
        t[ty + j * 8][tx] = W[(size_t)k * On + n0 + tx];
    }
    __syncthreads();
#pragma unroll
    for (int j = 0; j < 4; j++) {
        int n = n0 + ty + j * 8;
        float v = t[tx][ty + j * 8];
        g_Wt[(size_t)n * Fk + k0 + tx] = __float2half_rn(v);
    }
}

// ------------ kernel 2: fused init + split-K fp16 mma.sync GEMM ------------
__global__ void __launch_bounds__(256, 1)
gemm_kernel(const float* __restrict__ x, const float* __restrict__ W,
            const float* __restrict__ b, const float* __restrict__ coeff,
            const int* __restrict__ idx, const int* __restrict__ bitpos,
            float* __restrict__ out) {
    extern __shared__ char smem[];
    __shared__ float us[32];
    char* rawA = smem + OFF_RAWA;
    char* BS   = smem + OFF_B;
    char* Ac   = smem + OFF_AC;

    const int tid = threadIdx.x;
    const int lane = tid & 31, w = tid >> 5;
    const int wm = w & 1, wn = w >> 1;       // warp grid 2(M) x 4(N), 64x64 tile
    const int g = lane >> 2, q = lane & 3;

    const int m0 = blockIdx.x * BM;
    const int z  = blockIdx.z;
    const int kbase = z * K_PER_CTA;

    // ---- fused init: rows [m0+32z, m0+32z+32) of out = b + coeff*u*W[idx]
    // Safe: grid=128 CTAs <= 148 SMs at occ 1 -> single wave; all inits
    // complete ~1us after launch, first epilogue atomic lands ~150us later.
    {
        int r0 = m0 + z * 32;
        if (tid < 32) {
            int r = r0 + tid;
            int j = idx[r];
            float gg = x[(size_t)r * Fk + j];
            int gi = __float_as_int(gg) ^ (1 << bitpos[r]);
            us[tid] = (__int_as_float(gi) - gg) * coeff[0];
        }
        __syncthreads();
#pragma unroll
        for (int i = 0; i < 32; i++) {
            int e = tid + i * 256;
            int rr = e >> 8, c = e & 255;
            int r = r0 + rr;
            out[(size_t)r * On + c] =
                b[c] + us[rr] * W[(size_t)idx[r] * On + c];
        }
    }

    // ldmatrix per-lane address components (row within 16, k-16B half)
    const int lrow = lane & 15;
    const int lk16 = (lane >> 4) * 16;

    float acc[4][8][4];
#pragma unroll
    for (int i = 0; i < 4; i++)
#pragma unroll
        for (int j = 0; j < 8; j++)
#pragma unroll
            for (int r = 0; r < 4; r++) acc[i][j][r] = 0.0f;

    // ---- stage loader (always commits one group) ----
    auto issue = [&](int kt, int slot) {
        if (kt < NT) {
            const float* xg = x + (size_t)m0 * Fk + kbase + kt * BK;
            char* ra = rawA + slot * RAWA_STAGE;
#pragma unroll
            for (int i = 0; i < 4; i++) {
                int ch = tid + i * 256;           // 0..1023
                int row = ch >> 3, sub = ch & 7;
                int phys = sub ^ (row & 7);       // XOR swizzle (bank-free reads)
                cp_async16(ra + row * 128 + phys * 16,
                           xg + (size_t)row * Fk + sub * 4);
            }
            const __half* wt = g_Wt + kbase + kt * BK;
            char* bs = BS + slot * B_STAGE;
#pragma unroll
            for (int i = 0; i < 4; i++) {
                int ch = tid + i * 256;           // 0..1023
                int row = ch >> 2, sub = ch & 3;  // row 0..255
                cp_async16(bs + row * BROW_PITCH + sub * 16,
                           wt + (size_t)row * Fk + sub * 8);
            }
        }
        cp_commit();
    };

    issue(0, 0); issue(1, 1); issue(2, 2); issue(3, 3);

    // convert-thread mapping: conflict-free LDS.128 + STS.128
    const int crow = (w & 3) * 32 + lane;   // 0..127
    const int chh  = w >> 2;                // half of the 32-float row

    int slot = 0;       // slot of stage kt
    int pslot = 4;      // slot for prefetch stage kt+4
    for (int kt = 0; kt < NT; kt++) {
        cp_wait<3>();            // groups: 4+kt committed; group kt complete
        __syncthreads();         // data visible; mma of kt-1 done (slot reuse)

        issue(kt + 4, pslot);
        if (++pslot == STAGES) pslot = 0;

        // ---- convert raw x fp32 -> fp16 in SMEM (each elem once) ----
        {
            const char* ra = rawA + slot * RAWA_STAGE;
            uint32_t pk[8];
#pragma unroll
            for (int i = 0; i < 4; i++) {
                int phys = (chh * 4 + i) ^ (crow & 7);
                float4 v = *(const float4*)(ra + crow * 128 + phys * 16);
                pk[i * 2]     = cvt_f16x2(v.y, v.x);
                pk[i * 2 + 1] = cvt_f16x2(v.w, v.z);
            }
            uint4* d = (uint4*)(Ac + crow * BROW_PITCH + chh * 32);
            d[0] = make_uint4(pk[0], pk[1], pk[2], pk[3]);
            d[1] = make_uint4(pk[4], pk[5], pk[6], pk[7]);
        }
        __syncthreads();

        // ---- MMA: 2 x k16, ldmatrix fragment loads ----
        const uint32_t aBase = smem_u32(Ac) +
            (wm * 64 + lrow) * BROW_PITCH + lk16;
        const uint32_t bBase = smem_u32(BS) + slot * B_STAGE +
            (wn * 64 + lrow) * BROW_PITCH + lk16;
#pragma unroll
        for (int kk = 0; kk < 2; kk++) {
            uint32_t af[4][4];
#pragma unroll
            for (int mt = 0; mt < 4; mt++)
                ldsm_x4(af[mt], aBase + mt * 16 * BROW_PITCH + kk * 32);
            uint32_t bf[8][2];
#pragma unroll
            for (int p = 0; p < 4; p++) {
                uint32_t r[4];
                ldsm_x4(r, bBase + p * 16 * BROW_PITCH + kk * 32);
                bf[2 * p][0] = r[0]; bf[2 * p + 1][0] = r[1];
                bf[2 * p][1] = r[2]; bf[2 * p + 1][1] = r[3];
            }
#pragma unroll
            for (int mt = 0; mt < 4; mt++)
#pragma unroll
                for (int nt = 0; nt < 8; nt++)
                    mma_f16(acc[mt][nt], af[mt], bf[nt]);
        }

        if (++slot == STAGES) slot = 0;
    }

    cp_wait<0>();  // drain outstanding cp.async before exit

    // ---- epilogue: atomicAdd into initialized out ----
#pragma unroll
    for (int mt = 0; mt < 4; mt++) {
        int r0 = m0 + wm * 64 + mt * 16 + g;
#pragma unroll
        for (int nt = 0; nt < 8; nt++) {
            int col = wn * 64 + nt * 8 + q * 2;
            float* p0 = out + (size_t)r0 * On + col;
            float* p1 = out + (size_t)(r0 + 8) * On + col;
            atomicAdd(p0,     acc[mt][nt][0]);
            atomicAdd(p0 + 1, acc[mt][nt][1]);
            atomicAdd(p1,     acc[mt][nt][2]);
            atomicAdd(p1 + 1, acc[mt][nt][3]);
        }
    }
}

// ---------------------------------------------------------------------------
extern "C" void kernel_launch(void* const* d_in, const int* in_sizes, int n_in,
                              void* d_out, int out_size) {
    const float* x      = (const float*)d_in[0];
    const float* W      = (const float*)d_in[1];
    const float* b      = (const float*)d_in[2];
    const float* coeff  = (const float*)d_in[3];
    const int*   idx    = (const int*)d_in[4];
    const int*   bitpos = (const int*)d_in[5];
    float* out = (float*)d_out;

    cudaFuncSetAttribute(gemm_kernel,
                         cudaFuncAttributeMaxDynamicSharedMemorySize,
                         SMEM_TOTAL);

    // 1) W -> transposed fp16 scratch
    prep_w_kernel<<<dim3(On / 32, Fk / 32), dim3(32, 8)>>>(W);
    // 2) fused init (rank-1 correction + bias) + split-K GEMM
    gemm_kernel<<<dim3(Bm / BM, 1, SPLITK), 256, SMEM_TOTAL>>>(
        x, W, b, coeff, idx, bitpos, out);
}